// round 17
// baseline (speedup 1.0000x reference)
#include <cuda_runtime.h>
#include <stdint.h>

// StridedSlice: out[n,c,h,w] = x[n,c,2h,2w]
//   in : (8,128,512,512) f32   in row = 128 float4, plane = 65536 float4
//   out: (8,128,256,256) f32   out row = 64 float4, 262144 rows total
//
// FINAL (verified 3x: ncu 108.5/108.6/108.9 us, DRAM 87.5-87.7%, occ ~96%).
// Reads: SM-issued LDG.256 at 32 B lane stride — sector-exact (every DRAM
// sector fetched is fully consumed; read traffic at its 512 MiB floor) and
// massively parallel across ~4700 warps (engine-driven reads measured 10%
// slower, R14; per-warp bulk stores slower, R16). Writes: each block stages
// its 16 contiguous output rows (16 KB) in SMEM and drains them with ONE
// cp.async.bulk shared->global — coarse sequential bursts decoupled from
// load issue (best measured write path across STG.128/STG.256/TMA 2-32 KB).
// Total DRAM traffic = 768 MiB, the floor for this op; achieved ~6.93 TB/s.

__device__ __forceinline__ void ldg256(const float4* __restrict__ p,
                                       float4& v0, float4& v1)
{
    asm volatile("ld.global.v8.f32 {%0,%1,%2,%3,%4,%5,%6,%7}, [%8];"
                 : "=f"(v0.x), "=f"(v0.y), "=f"(v0.z), "=f"(v0.w),
                   "=f"(v1.x), "=f"(v1.y), "=f"(v1.z), "=f"(v1.w)
                 : "l"(p));
}

__global__ __launch_bounds__(256) void strided_slice_kernel(
    const float4* __restrict__ in, float4* __restrict__ out)
{
    __shared__ __align__(128) float4 tile[1024];   // 16 KB staging

    unsigned tid = threadIdx.x;
    unsigned w   = tid >> 5;        // warp 0..7
    unsigned t   = tid & 31u;

    unsigned R  = blockIdx.x << 4;  // first of 16 output rows for this block
    unsigned h  = R & 255u;         // multiple of 16; all rows in one plane
    unsigned nc = R >> 8;

    const float4* __restrict__ ib = in + ((size_t)nc << 16) + ((size_t)h << 8);

    unsigned j0 = w << 1;           // this warp's 2 local rows: j0, j0+1
    unsigned t2 = t << 1;

    // ---- load + decimate + stage (front-batched LDG.256) ----
    const float4* p0 = ib + j0 * 256;          // input row 2(h+j0)
    float4 a0, a1, a2, a3, b0, b1, b2, b3;
    ldg256(p0 + t2,        a0, a1);            // row j0,   out cols 0..31
    ldg256(p0 + t2 + 64,   a2, a3);            // row j0,   out cols 32..63
    ldg256(p0 + t2 + 256,  b0, b1);            // row j0+1, out cols 0..31
    ldg256(p0 + t2 + 320,  b2, b3);            // row j0+1, out cols 32..63

    float4* s = tile + j0 * 64;                // linear output layout in smem
    s[t]       = make_float4(a0.x, a0.z, a1.x, a1.z);
    s[32 + t]  = make_float4(a2.x, a2.z, a3.x, a3.z);
    s[64 + t]  = make_float4(b0.x, b0.z, b1.x, b1.z);
    s[96 + t]  = make_float4(b2.x, b2.z, b3.x, b3.z);

    __syncthreads();

    // ---- single 16 KB bulk store for the whole block ----
    if (tid == 0) {
        uint32_t saddr;
        asm("{ .reg .u64 x; cvta.to.shared.u64 x, %1; cvt.u32.u64 %0, x; }"
            : "=r"(saddr) : "l"(tile));
        const float4* g = out + ((size_t)R << 6);
        asm volatile("fence.proxy.async.shared::cta;" ::: "memory");
        asm volatile("cp.async.bulk.global.shared::cta.bulk_group [%0], [%1], 16384;"
                     :: "l"(g), "r"(saddr) : "memory");
        asm volatile("cp.async.bulk.commit_group;" ::: "memory");
        // release SMEM as soon as TMA has READ it (don't wait for write landing)
        asm volatile("cp.async.bulk.wait_group.read 0;" ::: "memory");
    }
    __syncthreads();   // no thread exits before SMEM is safe to retire
}

extern "C" void kernel_launch(void* const* d_in, const int* in_sizes, int n_in,
                              void* d_out, int out_size)
{
    (void)in_sizes; (void)n_in; (void)out_size;
    const float4* in  = (const float4*)d_in[0];
    float4*       out = (float4*)d_out;

    // 262144 output rows / 16 rows per block = 16384 blocks of 256 threads
    strided_slice_kernel<<<16384, 256>>>(in, out);
}